// round 12
// baseline (speedup 1.0000x reference)
#include <cuda_runtime.h>
#include <cuda_bf16.h>

// Problem constants (fixed by dataset)
constexpr int Bb = 8;
constexpr int Nn = 8192;
constexpr int Mm = 2048;
constexpr int Cc = 64;
constexpr int Kk = 32;

// Spatial grid: 8x8x8 cells of 0.125 (>= radius 0.1 -> 27-cell neighborhood exact)
constexpr int Gg    = 8;
constexpr int CELLS = Gg * Gg * Gg;        // 512
constexpr int BINS  = Bb * CELLS;          // 4096
constexpr int NPTS  = Bb * Nn;             // 65536
constexpr int CAP   = 128;                 // max hits/query (lambda~34)
constexpr int SENT  = 0x3FFFFFFF;

// Scratch (__device__ globals: no allocs allowed; zero-initialized at load)
__device__ float  g_feat_t[Bb * Nn * Cc];            // transposed features (B,N,C)
__device__ float4 g_pts[NPTS];                       // (x,y,z,n2) original order
__device__ int    g_binid[NPTS];                     // rank<<12 | bin
__device__ __align__(16) int g_cnt[BINS];            // histogram; re-zeroed by scan
__device__ __align__(16) int g_start[BINS + 4];      // padded for int4 stores
__device__ float4 g_spts[NPTS];                      // grid-sorted (x,y,z,pid)

// ---------------------------------------------------------------------------
// Fused: blocks [0, 1024) transpose feature (B,C,N)->(B,N,C) in 64x64 tiles;
// blocks [1024, 1280) pack points (x,y,z,n2) + histogram (rank from atomicAdd).
// ---------------------------------------------------------------------------
constexpr int TP_BLOCKS = (Nn / 64) * Bb;   // 1024

__global__ __launch_bounds__(256) void prep_transpose_kernel(
    const float* __restrict__ xyz, const float* __restrict__ feat)
{
    __shared__ float tile[64][65];
    const int t = threadIdx.x;

    if (blockIdx.x < TP_BLOCKS) {
        const int b  = blockIdx.x >> 7;
        const int n0 = (blockIdx.x & 127) * 64;
        const int j4 = (t & 15) * 4;
        #pragma unroll
        for (int p = 0; p < 4; ++p) {
            const int row = p * 16 + (t >> 4);     // channel
            const float4 v = *(const float4*)&feat[((size_t)(b * Cc + row)) * Nn + n0 + j4];
            tile[row][j4 + 0] = v.x; tile[row][j4 + 1] = v.y;
            tile[row][j4 + 2] = v.z; tile[row][j4 + 3] = v.w;
        }
        __syncthreads();
        #pragma unroll
        for (int p = 0; p < 4; ++p) {
            const int r = p * 16 + (t >> 4);       // point within tile
            float4 v;
            v.x = tile[j4 + 0][r]; v.y = tile[j4 + 1][r];
            v.z = tile[j4 + 2][r]; v.w = tile[j4 + 3][r];
            *(float4*)&g_feat_t[((size_t)(b * Nn + n0 + r)) * Cc + j4] = v;
        }
    } else {
        const int i = (blockIdx.x - TP_BLOCKS) * 256 + t;   // 0 .. NPTS-1
        const int b = i >> 13;
        const int n = i & (Nn - 1);
        const float x = xyz[(b * 3 + 0) * Nn + n];
        const float y = xyz[(b * 3 + 1) * Nn + n];
        const float z = xyz[(b * 3 + 2) * Nn + n];
        const float n2 = __fadd_rn(__fadd_rn(__fmul_rn(x, x), __fmul_rn(y, y)),
                                   __fmul_rn(z, z));
        g_pts[i] = make_float4(x, y, z, n2);
        const int cx = min(Gg - 1, max(0, (int)(x * Gg)));
        const int cy = min(Gg - 1, max(0, (int)(y * Gg)));
        const int cz = min(Gg - 1, max(0, (int)(z * Gg)));
        const int bin = b * CELLS + ((cz * Gg + cy) * Gg + cx);
        const int rank = atomicAdd(&g_cnt[bin], 1);   // rank doubles as scatter slot
        g_binid[i] = (rank << 12) | bin;
    }
}

// ---------------------------------------------------------------------------
// Exclusive scan of 4096 bins (256 thr x 16, int4); re-zeroes g_cnt for the
// next run (graph replays re-execute the whole sequence).
// ---------------------------------------------------------------------------
__global__ __launch_bounds__(256) void scan_kernel() {
    __shared__ int wsum[8];
    const int t = threadIdx.x, lane = t & 31, w = t >> 5;
    int vals[16];
    #pragma unroll
    for (int k = 0; k < 4; ++k) {
        const int4 v = *(const int4*)&g_cnt[t * 16 + k * 4];
        vals[k * 4 + 0] = v.x; vals[k * 4 + 1] = v.y;
        vals[k * 4 + 2] = v.z; vals[k * 4 + 3] = v.w;
    }
    #pragma unroll
    for (int k = 0; k < 4; ++k)
        *(int4*)&g_cnt[t * 16 + k * 4] = make_int4(0, 0, 0, 0);
    int sum = 0;
    int pre[16];
    #pragma unroll
    for (int k = 0; k < 16; ++k) { pre[k] = sum; sum += vals[k]; }
    int incl = sum;
    #pragma unroll
    for (int off = 1; off < 32; off <<= 1) {
        const int x = __shfl_up_sync(0xffffffffu, incl, off);
        if (lane >= off) incl += x;
    }
    if (lane == 31) wsum[w] = incl;
    __syncthreads();
    if (t == 0) {
        int acc = 0;
        #pragma unroll
        for (int i = 0; i < 8; ++i) { const int x = wsum[i]; wsum[i] = acc; acc += x; }
        g_start[BINS] = acc;
    }
    __syncthreads();
    const int excl = wsum[w] + incl - sum;
    #pragma unroll
    for (int k = 0; k < 4; ++k) {
        int4 o;
        o.x = excl + pre[k * 4 + 0]; o.y = excl + pre[k * 4 + 1];
        o.z = excl + pre[k * 4 + 2]; o.w = excl + pre[k * 4 + 3];
        *(int4*)&g_start[t * 16 + k * 4] = o;
    }
}

// Atomic-free scatter: slot = g_start[bin] + rank (rank captured in prep).
// 2 points per thread for MLP; pid packed into spts.w.
__global__ __launch_bounds__(256) void scatter_kernel() {
    const int t0 = blockIdx.x * blockDim.x + threadIdx.x;
    #pragma unroll
    for (int k = 0; k < 2; ++k) {
        const int t = t0 + k * (NPTS / 2);
        const int br = g_binid[t];
        const int pos = g_start[br & 4095] + (br >> 12);
        float4 p = g_pts[t];
        p.w = __int_as_float(t & (Nn - 1));
        g_spts[pos] = p;
    }
}

// ---------------------------------------------------------------------------
// Fused select + output, fully warp-autonomous (no __syncthreads).
// Block = 256 thr = 8 warps = 8 queries; each warp: select -> output.
// Select: grid-pruned exact ball query (cell culling) + warp bitonic sort-128.
// Output: per-warp smem slab [32][33] (conflict-free), 2 channel-halves.
// ---------------------------------------------------------------------------
__global__ __launch_bounds__(256) void group_kernel(
    const float* __restrict__ new_xyz,
    float* __restrict__ out)
{
    const int b      = blockIdx.y;
    const int m_base = blockIdx.x * 8;
    const int tid    = threadIdx.x;
    const int wid    = tid >> 5;
    const int lane   = tid & 31;

    __shared__ int   cand[8][CAP];
    __shared__ int   idx_sh[8][Kk];
    __shared__ float f_s[8][Kk][33];   // per-warp slab; stride 33 -> bank j+c (CF)

    // ---- SELECT (warp <-> query) ----
    const int m = m_base + wid;
    const float qx = new_xyz[(b * 3 + 0) * Mm + m];
    const float qy = new_xyz[(b * 3 + 1) * Mm + m];
    const float qz = new_xyz[(b * 3 + 2) * Mm + m];
    const float m2 = __fadd_rn(__fadd_rn(__fmul_rn(qx, qx), __fmul_rn(qy, qy)),
                               __fmul_rn(qz, qz));

    const int qcx = min(Gg - 1, max(0, (int)(qx * Gg)));
    const int qcy = min(Gg - 1, max(0, (int)(qy * Gg)));
    const int qcz = min(Gg - 1, max(0, (int)(qz * Gg)));
    const unsigned lmask_lt = (1u << lane) - 1u;

    // Face distances to the +/-1 cell rings (cell size h = 0.125).
    constexpr float Hh  = 0.125f;
    constexpr float R2M = 0.0101f;   // cull bound: 0.01 + margin >> fp error (~2e-6)
    const float dxl = qx - qcx * Hh,  dxh = (qcx + 1) * Hh - qx;
    const float dyl = qy - qcy * Hh,  dyh = (qcy + 1) * Hh - qy;
    const float dzl = qz - qcz * Hh,  dzh = (qcz + 1) * Hh - qz;
    const float dxl2 = dxl * dxl, dxh2 = dxh * dxh;
    const float dyl2 = dyl * dyl, dyh2 = dyh * dyh;
    const float dzl2 = dzl * dzl, dzh2 = dzh * dzh;

    const int z0 = max(0, qcz - 1), z1 = min(Gg - 1, qcz + 1);
    const int y0 = max(0, qcy - 1), y1 = min(Gg - 1, qcy + 1);

    int cand_cnt = 0;
    for (int cz = z0; cz <= z1; ++cz) {
        const float dz2 = (cz < qcz) ? dzl2 : ((cz > qcz) ? dzh2 : 0.0f);
        for (int cy = y0; cy <= y1; ++cy) {
            const float dy2 = (cy < qcy) ? dyl2 : ((cy > qcy) ? dyh2 : 0.0f);
            const float dyz2 = dy2 + dz2;
            if (dyz2 >= R2M) continue;                     // row can't touch the ball
            int xlo = qcx, xhi = qcx;
            if (qcx > 0        && dxl2 + dyz2 < R2M) xlo = qcx - 1;
            if (qcx < Gg - 1   && dxh2 + dyz2 < R2M) xhi = qcx + 1;
            const int row = b * CELLS + (cz * Gg + cy) * Gg;
            const int s = g_start[row + xlo];
            const int e = g_start[row + xhi + 1];          // x-cells contiguous
            for (int base = s; base < e; base += 32) {
                const int i = base + lane;
                bool in = false;
                int pid = 0;
                if (i < e) {
                    const float4 p = g_spts[i];
                    pid = __float_as_int(p.w);
                    // n2 recomputed with the exact reference rounding chain
                    const float n2 = __fadd_rn(__fadd_rn(__fmul_rn(p.x, p.x),
                                                         __fmul_rn(p.y, p.y)),
                                               __fmul_rn(p.z, p.z));
                    const float dot = __fmaf_rn(qz, p.z,
                                      __fmaf_rn(qy, p.y, __fmul_rn(qx, p.x)));
                    const float d2  = __fsub_rn(__fadd_rn(m2, n2), __fmul_rn(2.0f, dot));
                    in = d2 < 0.01f;
                }
                const unsigned mask = __ballot_sync(0xffffffffu, in);
                if (in) {
                    const int pos = cand_cnt + __popc(mask & lmask_lt);
                    if (pos < CAP) cand[wid][pos] = pid;
                }
                cand_cnt += __popc(mask);
            }
        }
    }
    if (cand_cnt > CAP) cand_cnt = CAP;
    __syncwarp();

    // ---- Warp bitonic sort of 128 values (4/lane, blocked: i = lane*4+k) ----
    int a[4];
    #pragma unroll
    for (int k = 0; k < 4; ++k) {
        const int p = lane * 4 + k;
        a[k] = (p < cand_cnt) ? cand[wid][p] : SENT;
    }
    {   // lane-local sort-4 ascending (replaces bitonic sizes 2 and 4)
        int lo, hi;
        lo = min(a[0], a[1]); hi = max(a[0], a[1]); a[0] = lo; a[1] = hi;
        lo = min(a[2], a[3]); hi = max(a[2], a[3]); a[2] = lo; a[3] = hi;
        lo = min(a[0], a[2]); hi = max(a[0], a[2]); a[0] = lo; a[2] = hi;
        lo = min(a[1], a[3]); hi = max(a[1], a[3]); a[1] = lo; a[3] = hi;
        lo = min(a[1], a[2]); hi = max(a[1], a[2]); a[1] = lo; a[2] = hi;
        if (lane & 1) {   // odd lanes descending -> alternating 4-runs
            int t0 = a[0]; a[0] = a[3]; a[3] = t0;
            int t1 = a[1]; a[1] = a[2]; a[2] = t1;
        }
    }
    #pragma unroll
    for (int size = 8; size <= 128; size <<= 1) {
        const bool dirUp = (lane & (size >> 2)) == 0;   // (i & size) == 0
        #pragma unroll
        for (int stride = size >> 1; stride >= 4; stride >>= 1) {
            const int  xl      = stride >> 2;
            const bool keepMin = (dirUp == ((lane & xl) == 0));
            #pragma unroll
            for (int k = 0; k < 4; ++k) {
                const int w = __shfl_xor_sync(0xffffffffu, a[k], xl);
                a[k] = keepMin ? min(a[k], w) : max(a[k], w);
            }
        }
        {   // stride 2: pairs (0,2),(1,3)
            int lo0 = min(a[0], a[2]), hi0 = max(a[0], a[2]);
            int lo1 = min(a[1], a[3]), hi1 = max(a[1], a[3]);
            a[0] = dirUp ? lo0 : hi0;  a[2] = dirUp ? hi0 : lo0;
            a[1] = dirUp ? lo1 : hi1;  a[3] = dirUp ? hi1 : lo1;
        }
        {   // stride 1: pairs (0,1),(2,3)
            int lo0 = min(a[0], a[1]), hi0 = max(a[0], a[1]);
            int lo1 = min(a[2], a[3]), hi1 = max(a[2], a[3]);
            a[0] = dirUp ? lo0 : hi0;  a[1] = dirUp ? hi0 : lo0;
            a[2] = dirUp ? lo1 : hi1;  a[3] = dirUp ? hi1 : lo1;
        }
    }
    // Fully ascending: smallest 32 live in lanes 0-7. Pad + publish.
    {
        int first = __shfl_sync(0xffffffffu, a[0], 0);
        first = (first >= Nn) ? 0 : first;
        if (lane < 8) {
            #pragma unroll
            for (int k = 0; k < 4; ++k) {
                const int v = (a[k] >= Nn) ? first : a[k];
                idx_sh[wid][lane * 4 + k] = v;
            }
        }
    }
    __syncwarp();

    // ---- OUTPUT (per-warp, lane <-> neighbor j) ----
    const int nj = idx_sh[wid][lane];
    const float4* __restrict__ ft4 = (const float4*)(g_feat_t + (size_t)b * Nn * Cc)
                                     + (size_t)nj * 16;
    const size_t GX = (size_t)Bb * 67 * Mm * Kk;

    // group_xyz straight from registers (q coords warp-uniform)
    {
        const float4 p = g_pts[b * Nn + nj];
        const float gx = __fsub_rn(p.x, qx);
        const float gy = __fsub_rn(p.y, qy);
        const float gz = __fsub_rn(p.z, qz);
        const size_t base0 = (((size_t)(b * 67 + 64)) * Mm + m) * Kk + lane;
        const size_t baseG = GX + (((size_t)(b * 3)) * Mm + m) * Kk + lane;
        const size_t step  = (size_t)Mm * Kk;
        __stcs(&out[base0 + 0 * step], gx);
        __stcs(&out[base0 + 1 * step], gy);
        __stcs(&out[base0 + 2 * step], gz);
        __stcs(&out[baseG + 0 * step], gx);
        __stcs(&out[baseG + 1 * step], gy);
        __stcs(&out[baseG + 2 * step], gz);
    }

    // features in two 32-channel halves
    #pragma unroll 1
    for (int h = 0; h < 2; ++h) {
        // stage: lane j loads its neighbor's 8 float4 (128B contiguous)
        #pragma unroll
        for (int cc = 0; cc < 8; ++cc) {
            const float4 v = ft4[h * 8 + cc];
            f_s[wid][lane][cc * 4 + 0] = v.x;
            f_s[wid][lane][cc * 4 + 1] = v.y;
            f_s[wid][lane][cc * 4 + 2] = v.z;
            f_s[wid][lane][cc * 4 + 3] = v.w;
        }
        __syncwarp();
        // write: lane covers (c_local = it*4 + lane>>3, j4 = (lane&7)*4)
        #pragma unroll
        for (int it = 0; it < 8; ++it) {
            const int cl = it * 4 + (lane >> 3);
            const int j4 = (lane & 7) * 4;
            float4 v;
            v.x = f_s[wid][j4 + 0][cl];
            v.y = f_s[wid][j4 + 1][cl];
            v.z = f_s[wid][j4 + 2][cl];
            v.w = f_s[wid][j4 + 3][cl];
            __stcs((float4*)&out[(((size_t)(b * 67 + h * 32 + cl)) * Mm + m) * Kk + j4], v);
        }
        __syncwarp();
    }
}

// ---------------------------------------------------------------------------
extern "C" void kernel_launch(void* const* d_in, const int* in_sizes, int n_in,
                              void* d_out, int out_size) {
    const float* new_xyz = (const float*)d_in[0];   // (8, 3, 2048)
    const float* xyz     = (const float*)d_in[1];   // (8, 3, 8192)
    const float* feat    = (const float*)d_in[2];   // (8, 64, 8192)
    float* out = (float*)d_out;

    prep_transpose_kernel<<<TP_BLOCKS + NPTS / 256, 256>>>(xyz, feat);
    scan_kernel<<<1, 256>>>();
    scatter_kernel<<<(NPTS / 2) / 256, 256>>>();
    group_kernel<<<dim3(Mm / 8, Bb), 256>>>(new_xyz, out);
}

// round 13
// speedup vs baseline: 1.0811x; 1.0811x over previous
#include <cuda_runtime.h>
#include <cuda_bf16.h>

// Problem constants (fixed by dataset)
constexpr int Bb = 8;
constexpr int Nn = 8192;
constexpr int Mm = 2048;
constexpr int Cc = 64;
constexpr int Kk = 32;

// Spatial grid: 8x8x8 cells of 0.125 (>= radius 0.1 -> 27-cell neighborhood exact)
constexpr int Gg    = 8;
constexpr int CELLS = Gg * Gg * Gg;        // 512
constexpr int BINS  = Bb * CELLS;          // 4096
constexpr int NPTS  = Bb * Nn;             // 65536
constexpr int CAP   = 128;                 // max hits/query (lambda~34)
constexpr int SENT  = 0x3FFFFFFF;

// Scratch (__device__ globals: no allocs allowed; zero-initialized at load)
__device__ float  g_feat_t[Bb * Nn * Cc];            // transposed features (B,N,C)
__device__ float4 g_pts[NPTS];                       // (x,y,z,n2) original order
__device__ int    g_binid[NPTS];                     // rank<<12 | bin
__device__ __align__(16) int g_cnt[BINS];            // histogram; re-zeroed by scan
__device__ __align__(16) int g_start[BINS + 4];      // padded for int4 stores
__device__ float4 g_spts[NPTS];                      // grid-sorted (x,y,z,pid)

// ---------------------------------------------------------------------------
// Fused: blocks [0, 1024) transpose feature (B,C,N)->(B,N,C) in 64x64 tiles;
// blocks [1024, 1280) pack points (x,y,z,n2) + histogram (rank from atomicAdd).
// ---------------------------------------------------------------------------
constexpr int TP_BLOCKS = (Nn / 64) * Bb;   // 1024

__global__ __launch_bounds__(256) void prep_transpose_kernel(
    const float* __restrict__ xyz, const float* __restrict__ feat)
{
    __shared__ float tile[64][65];
    const int t = threadIdx.x;

    if (blockIdx.x < TP_BLOCKS) {
        const int b  = blockIdx.x >> 7;
        const int n0 = (blockIdx.x & 127) * 64;
        const int j4 = (t & 15) * 4;
        #pragma unroll
        for (int p = 0; p < 4; ++p) {
            const int row = p * 16 + (t >> 4);     // channel
            const float4 v = *(const float4*)&feat[((size_t)(b * Cc + row)) * Nn + n0 + j4];
            tile[row][j4 + 0] = v.x; tile[row][j4 + 1] = v.y;
            tile[row][j4 + 2] = v.z; tile[row][j4 + 3] = v.w;
        }
        __syncthreads();
        #pragma unroll
        for (int p = 0; p < 4; ++p) {
            const int r = p * 16 + (t >> 4);       // point within tile
            float4 v;
            v.x = tile[j4 + 0][r]; v.y = tile[j4 + 1][r];
            v.z = tile[j4 + 2][r]; v.w = tile[j4 + 3][r];
            *(float4*)&g_feat_t[((size_t)(b * Nn + n0 + r)) * Cc + j4] = v;
        }
    } else {
        const int i = (blockIdx.x - TP_BLOCKS) * 256 + t;   // 0 .. NPTS-1
        const int b = i >> 13;
        const int n = i & (Nn - 1);
        const float x = xyz[(b * 3 + 0) * Nn + n];
        const float y = xyz[(b * 3 + 1) * Nn + n];
        const float z = xyz[(b * 3 + 2) * Nn + n];
        const float n2 = __fadd_rn(__fadd_rn(__fmul_rn(x, x), __fmul_rn(y, y)),
                                   __fmul_rn(z, z));
        g_pts[i] = make_float4(x, y, z, n2);
        const int cx = min(Gg - 1, max(0, (int)(x * Gg)));
        const int cy = min(Gg - 1, max(0, (int)(y * Gg)));
        const int cz = min(Gg - 1, max(0, (int)(z * Gg)));
        const int bin = b * CELLS + ((cz * Gg + cy) * Gg + cx);
        const int rank = atomicAdd(&g_cnt[bin], 1);   // rank doubles as scatter slot
        g_binid[i] = (rank << 12) | bin;
    }
}

// ---------------------------------------------------------------------------
// Exclusive scan of 4096 bins (256 thr x 16, int4); re-zeroes g_cnt for the
// next run (graph replays re-execute the whole sequence).
// ---------------------------------------------------------------------------
__global__ __launch_bounds__(256) void scan_kernel() {
    __shared__ int wsum[8];
    const int t = threadIdx.x, lane = t & 31, w = t >> 5;
    int vals[16];
    #pragma unroll
    for (int k = 0; k < 4; ++k) {
        const int4 v = *(const int4*)&g_cnt[t * 16 + k * 4];
        vals[k * 4 + 0] = v.x; vals[k * 4 + 1] = v.y;
        vals[k * 4 + 2] = v.z; vals[k * 4 + 3] = v.w;
    }
    #pragma unroll
    for (int k = 0; k < 4; ++k)
        *(int4*)&g_cnt[t * 16 + k * 4] = make_int4(0, 0, 0, 0);
    int sum = 0;
    int pre[16];
    #pragma unroll
    for (int k = 0; k < 16; ++k) { pre[k] = sum; sum += vals[k]; }
    int incl = sum;
    #pragma unroll
    for (int off = 1; off < 32; off <<= 1) {
        const int x = __shfl_up_sync(0xffffffffu, incl, off);
        if (lane >= off) incl += x;
    }
    if (lane == 31) wsum[w] = incl;
    __syncthreads();
    if (t == 0) {
        int acc = 0;
        #pragma unroll
        for (int i = 0; i < 8; ++i) { const int x = wsum[i]; wsum[i] = acc; acc += x; }
        g_start[BINS] = acc;
    }
    __syncthreads();
    const int excl = wsum[w] + incl - sum;
    #pragma unroll
    for (int k = 0; k < 4; ++k) {
        int4 o;
        o.x = excl + pre[k * 4 + 0]; o.y = excl + pre[k * 4 + 1];
        o.z = excl + pre[k * 4 + 2]; o.w = excl + pre[k * 4 + 3];
        *(int4*)&g_start[t * 16 + k * 4] = o;
    }
}

// Atomic-free scatter: slot = g_start[bin] + rank (rank captured in prep).
// 2 points per thread for MLP; pid packed into spts.w.
__global__ __launch_bounds__(256) void scatter_kernel() {
    const int t0 = blockIdx.x * blockDim.x + threadIdx.x;
    #pragma unroll
    for (int k = 0; k < 2; ++k) {
        const int t = t0 + k * (NPTS / 2);
        const int br = g_binid[t];
        const int pos = g_start[br & 4095] + (br >> 12);
        float4 p = g_pts[t];
        p.w = __int_as_float(t & (Nn - 1));
        g_spts[pos] = p;
    }
}

// ---------------------------------------------------------------------------
// Fused select + output (R11 structure). Block = 256 thr = 8 warps = 8 queries.
// Select: warp-per-query ball query with per-cell ball-intersection culling
//         + warp bitonic sort-128.
// Output: scalar smem (conflict-free), 4 pair-iterations.
// ---------------------------------------------------------------------------
__global__ __launch_bounds__(256, 6) void group_kernel(
    const float* __restrict__ new_xyz,
    float* __restrict__ out)
{
    const int b      = blockIdx.y;
    const int m_base = blockIdx.x * 8;
    const int tid    = threadIdx.x;
    const int wid    = tid >> 5;
    const int lane   = tid & 31;

    __shared__ int    cand[8][CAP];
    __shared__ int    idx_sh[8][Kk];
    __shared__ float4 q_sh[8];
    __shared__ float  g_s[2][3][Kk];
    __shared__ float  f_s[2][Kk][Cc + 1];

    // ---- SELECT (warp <-> query) ----
    const int m = m_base + wid;
    const float qx = new_xyz[(b * 3 + 0) * Mm + m];
    const float qy = new_xyz[(b * 3 + 1) * Mm + m];
    const float qz = new_xyz[(b * 3 + 2) * Mm + m];
    const float m2 = __fadd_rn(__fadd_rn(__fmul_rn(qx, qx), __fmul_rn(qy, qy)),
                               __fmul_rn(qz, qz));
    if (lane == 0) q_sh[wid] = make_float4(qx, qy, qz, m2);

    const int qcx = min(Gg - 1, max(0, (int)(qx * Gg)));
    const int qcy = min(Gg - 1, max(0, (int)(qy * Gg)));
    const int qcz = min(Gg - 1, max(0, (int)(qz * Gg)));
    const unsigned lmask_lt = (1u << lane) - 1u;

    // Face distances to the +/-1 cell rings (cell size h = 0.125).
    constexpr float Hh  = 0.125f;
    constexpr float R2M = 0.0101f;   // cull bound: 0.01 + margin >> fp error (~2e-6)
    const float dxl = qx - qcx * Hh,  dxh = (qcx + 1) * Hh - qx;
    const float dyl = qy - qcy * Hh,  dyh = (qcy + 1) * Hh - qy;
    const float dzl = qz - qcz * Hh,  dzh = (qcz + 1) * Hh - qz;
    const float dxl2 = dxl * dxl, dxh2 = dxh * dxh;
    const float dyl2 = dyl * dyl, dyh2 = dyh * dyh;
    const float dzl2 = dzl * dzl, dzh2 = dzh * dzh;

    const int z0 = max(0, qcz - 1), z1 = min(Gg - 1, qcz + 1);
    const int y0 = max(0, qcy - 1), y1 = min(Gg - 1, qcy + 1);

    int cand_cnt = 0;
    for (int cz = z0; cz <= z1; ++cz) {
        const float dz2 = (cz < qcz) ? dzl2 : ((cz > qcz) ? dzh2 : 0.0f);
        for (int cy = y0; cy <= y1; ++cy) {
            const float dy2 = (cy < qcy) ? dyl2 : ((cy > qcy) ? dyh2 : 0.0f);
            const float dyz2 = dy2 + dz2;
            if (dyz2 >= R2M) continue;                     // row can't touch the ball
            int xlo = qcx, xhi = qcx;
            if (qcx > 0        && dxl2 + dyz2 < R2M) xlo = qcx - 1;
            if (qcx < Gg - 1   && dxh2 + dyz2 < R2M) xhi = qcx + 1;
            const int row = b * CELLS + (cz * Gg + cy) * Gg;
            const int s = g_start[row + xlo];
            const int e = g_start[row + xhi + 1];          // x-cells contiguous
            for (int base = s; base < e; base += 32) {
                const int i = base + lane;
                bool in = false;
                int pid = 0;
                if (i < e) {
                    const float4 p = g_spts[i];
                    pid = __float_as_int(p.w);
                    // n2 recomputed with the exact reference rounding chain
                    const float n2 = __fadd_rn(__fadd_rn(__fmul_rn(p.x, p.x),
                                                         __fmul_rn(p.y, p.y)),
                                               __fmul_rn(p.z, p.z));
                    const float dot = __fmaf_rn(qz, p.z,
                                      __fmaf_rn(qy, p.y, __fmul_rn(qx, p.x)));
                    const float d2  = __fsub_rn(__fadd_rn(m2, n2), __fmul_rn(2.0f, dot));
                    in = d2 < 0.01f;
                }
                const unsigned mask = __ballot_sync(0xffffffffu, in);
                if (in) {
                    const int pos = cand_cnt + __popc(mask & lmask_lt);
                    if (pos < CAP) cand[wid][pos] = pid;
                }
                cand_cnt += __popc(mask);
            }
        }
    }
    if (cand_cnt > CAP) cand_cnt = CAP;

    // ---- Warp bitonic sort of 128 values (4/lane, blocked: i = lane*4+k) ----
    int a[4];
    #pragma unroll
    for (int k = 0; k < 4; ++k) {
        const int p = lane * 4 + k;
        a[k] = (p < cand_cnt) ? cand[wid][p] : SENT;
    }
    {   // lane-local sort-4 ascending (replaces bitonic sizes 2 and 4)
        int lo, hi;
        lo = min(a[0], a[1]); hi = max(a[0], a[1]); a[0] = lo; a[1] = hi;
        lo = min(a[2], a[3]); hi = max(a[2], a[3]); a[2] = lo; a[3] = hi;
        lo = min(a[0], a[2]); hi = max(a[0], a[2]); a[0] = lo; a[2] = hi;
        lo = min(a[1], a[3]); hi = max(a[1], a[3]); a[1] = lo; a[3] = hi;
        lo = min(a[1], a[2]); hi = max(a[1], a[2]); a[1] = lo; a[2] = hi;
        if (lane & 1) {   // odd lanes descending -> alternating 4-runs
            int t0 = a[0]; a[0] = a[3]; a[3] = t0;
            int t1 = a[1]; a[1] = a[2]; a[2] = t1;
        }
    }
    #pragma unroll
    for (int size = 8; size <= 128; size <<= 1) {
        const bool dirUp = (lane & (size >> 2)) == 0;   // (i & size) == 0
        #pragma unroll
        for (int stride = size >> 1; stride >= 4; stride >>= 1) {
            const int  xl      = stride >> 2;
            const bool keepMin = (dirUp == ((lane & xl) == 0));
            #pragma unroll
            for (int k = 0; k < 4; ++k) {
                const int w = __shfl_xor_sync(0xffffffffu, a[k], xl);
                a[k] = keepMin ? min(a[k], w) : max(a[k], w);
            }
        }
        {   // stride 2: pairs (0,2),(1,3)
            int lo0 = min(a[0], a[2]), hi0 = max(a[0], a[2]);
            int lo1 = min(a[1], a[3]), hi1 = max(a[1], a[3]);
            a[0] = dirUp ? lo0 : hi0;  a[2] = dirUp ? hi0 : lo0;
            a[1] = dirUp ? lo1 : hi1;  a[3] = dirUp ? hi1 : lo1;
        }
        {   // stride 1: pairs (0,1),(2,3)
            int lo0 = min(a[0], a[1]), hi0 = max(a[0], a[1]);
            int lo1 = min(a[2], a[3]), hi1 = max(a[2], a[3]);
            a[0] = dirUp ? lo0 : hi0;  a[1] = dirUp ? hi0 : lo0;
            a[2] = dirUp ? lo1 : hi1;  a[3] = dirUp ? hi1 : lo1;
        }
    }
    // Fully ascending: smallest 32 live in lanes 0-7. Pad + publish.
    {
        int first = __shfl_sync(0xffffffffu, a[0], 0);
        first = (first >= Nn) ? 0 : first;
        if (lane < 8) {
            #pragma unroll
            for (int k = 0; k < 4; ++k) {
                const int v = (a[k] >= Nn) ? first : a[k];
                idx_sh[wid][lane * 4 + k] = v;
            }
        }
    }
    __syncthreads();

    // ---- OUTPUT: 4 pair-iterations, 2 queries concurrently ----
    const float4* __restrict__ pts = g_pts + b * Nn;
    const float*  __restrict__ ft  = g_feat_t + (size_t)b * Nn * Cc;
    const size_t GX = (size_t)Bb * 67 * Mm * Kk;

    #pragma unroll 1
    for (int pq = 0; pq < 4; ++pq) {
        const int q0 = pq * 2;

        if (tid < 2 * Kk) {
            const int q = tid >> 5, j = tid & 31;
            const float4 p  = pts[idx_sh[q0 + q][j]];
            const float4 Qd = q_sh[q0 + q];
            g_s[q][0][j] = __fsub_rn(p.x, Qd.x);
            g_s[q][1][j] = __fsub_rn(p.y, Qd.y);
            g_s[q][2][j] = __fsub_rn(p.z, Qd.z);
        }
        // stage features: float4 loads, 256B contiguous per neighbor
        #pragma unroll
        for (int l = tid; l < 2 * Kk * 16; l += 256) {
            const int q = l >> 9, j = (l >> 4) & 31, c4 = (l & 15) * 4;
            const float4 v = *(const float4*)&ft[(size_t)idx_sh[q0 + q][j] * Cc + c4];
            f_s[q][j][c4 + 0] = v.x; f_s[q][j][c4 + 1] = v.y;
            f_s[q][j][c4 + 2] = v.z; f_s[q][j][c4 + 3] = v.w;
        }
        __syncthreads();

        // feature channels c<64: float4 streaming writes over j
        #pragma unroll
        for (int o = tid; o < Cc * 2 * 8; o += 256) {
            const int c = o >> 4, q = (o >> 3) & 1, j4 = (o & 7) * 4;
            float4 v;
            v.x = f_s[q][j4 + 0][c]; v.y = f_s[q][j4 + 1][c];
            v.z = f_s[q][j4 + 2][c]; v.w = f_s[q][j4 + 3][c];
            __stcs((float4*)&out[(((size_t)(b * 67 + c)) * Mm + m_base + q0 + q) * Kk + j4], v);
        }
        // xyz channels (64..66) + appended group_xyz
        if (tid < 2 * 3 * Kk) {
            const int q = tid / 96, r = tid % 96;
            const int axis = r >> 5, j = r & 31;
            const float v = g_s[q][axis][j];
            const size_t mq = m_base + q0 + q;
            __stcs(&out[(((size_t)(b * 67 + 64 + axis)) * Mm + mq) * Kk + j], v);
            __stcs(&out[GX + (((size_t)(b * 3 + axis)) * Mm + mq) * Kk + j], v);
        }
        __syncthreads();   // before reusing f_s / g_s
    }
}

// ---------------------------------------------------------------------------
extern "C" void kernel_launch(void* const* d_in, const int* in_sizes, int n_in,
                              void* d_out, int out_size) {
    const float* new_xyz = (const float*)d_in[0];   // (8, 3, 2048)
    const float* xyz     = (const float*)d_in[1];   // (8, 3, 8192)
    const float* feat    = (const float*)d_in[2];   // (8, 64, 8192)
    float* out = (float*)d_out;

    // Raise the smem carveout so static smem stops capping blocks/SM.
    // Host-side attribute set: no alloc, deterministic, capture-legal.
    cudaFuncSetAttribute(group_kernel,
                         cudaFuncAttributePreferredSharedMemoryCarveout, 100);

    prep_transpose_kernel<<<TP_BLOCKS + NPTS / 256, 256>>>(xyz, feat);
    scan_kernel<<<1, 256>>>();
    scatter_kernel<<<(NPTS / 2) / 256, 256>>>();
    group_kernel<<<dim3(Mm / 8, Bb), 256>>>(new_xyz, out);
}

// round 14
// speedup vs baseline: 1.1434x; 1.0577x over previous
#include <cuda_runtime.h>
#include <cuda_bf16.h>

// Problem constants (fixed by dataset)
constexpr int Bb = 8;
constexpr int Nn = 8192;
constexpr int Mm = 2048;
constexpr int Cc = 64;
constexpr int Kk = 32;

// Spatial grid: 8x8x8 cells of 0.125 (>= radius 0.1 -> 27-cell neighborhood exact)
constexpr int Gg    = 8;
constexpr int CELLS = Gg * Gg * Gg;        // 512
constexpr int BINS  = Bb * CELLS;          // 4096
constexpr int NPTS  = Bb * Nn;             // 65536
constexpr int CAP   = 128;                 // max hits/query (lambda~34)
constexpr int SENT  = 0x3FFFFFFF;

// Scratch (__device__ globals: no allocs allowed; zero-initialized at load)
__device__ float  g_feat_t[Bb * Nn * Cc];            // transposed features (B,N,C)
__device__ float4 g_pts[NPTS];                       // (x,y,z,n2) original order
__device__ int    g_binid[NPTS];                     // rank<<12 | bin
__device__ __align__(16) int g_cnt[BINS];            // histogram; re-zeroed by scan
__device__ __align__(16) int g_start[BINS + 4];      // padded for int4 stores
__device__ float4 g_spts[NPTS];                      // grid-sorted (x,y,z,pid)

// ---------------------------------------------------------------------------
// Fused: blocks [0, 1024) transpose feature (B,C,N)->(B,N,C) in 64x64 tiles;
// blocks [1024, 1280) pack points (x,y,z,n2) + histogram (rank from atomicAdd).
// ---------------------------------------------------------------------------
constexpr int TP_BLOCKS = (Nn / 64) * Bb;   // 1024

__global__ __launch_bounds__(256) void prep_transpose_kernel(
    const float* __restrict__ xyz, const float* __restrict__ feat)
{
    __shared__ float tile[64][65];
    const int t = threadIdx.x;

    if (blockIdx.x < TP_BLOCKS) {
        const int b  = blockIdx.x >> 7;
        const int n0 = (blockIdx.x & 127) * 64;
        const int j4 = (t & 15) * 4;
        #pragma unroll
        for (int p = 0; p < 4; ++p) {
            const int row = p * 16 + (t >> 4);     // channel
            const float4 v = *(const float4*)&feat[((size_t)(b * Cc + row)) * Nn + n0 + j4];
            tile[row][j4 + 0] = v.x; tile[row][j4 + 1] = v.y;
            tile[row][j4 + 2] = v.z; tile[row][j4 + 3] = v.w;
        }
        __syncthreads();
        #pragma unroll
        for (int p = 0; p < 4; ++p) {
            const int r = p * 16 + (t >> 4);       // point within tile
            float4 v;
            v.x = tile[j4 + 0][r]; v.y = tile[j4 + 1][r];
            v.z = tile[j4 + 2][r]; v.w = tile[j4 + 3][r];
            *(float4*)&g_feat_t[((size_t)(b * Nn + n0 + r)) * Cc + j4] = v;
        }
    } else {
        const int i = (blockIdx.x - TP_BLOCKS) * 256 + t;   // 0 .. NPTS-1
        const int b = i >> 13;
        const int n = i & (Nn - 1);
        const float x = xyz[(b * 3 + 0) * Nn + n];
        const float y = xyz[(b * 3 + 1) * Nn + n];
        const float z = xyz[(b * 3 + 2) * Nn + n];
        const float n2 = __fadd_rn(__fadd_rn(__fmul_rn(x, x), __fmul_rn(y, y)),
                                   __fmul_rn(z, z));
        g_pts[i] = make_float4(x, y, z, n2);
        const int cx = min(Gg - 1, max(0, (int)(x * Gg)));
        const int cy = min(Gg - 1, max(0, (int)(y * Gg)));
        const int cz = min(Gg - 1, max(0, (int)(z * Gg)));
        const int bin = b * CELLS + ((cz * Gg + cy) * Gg + cx);
        const int rank = atomicAdd(&g_cnt[bin], 1);   // rank doubles as scatter slot
        g_binid[i] = (rank << 12) | bin;
    }
}

// ---------------------------------------------------------------------------
// Exclusive scan of 4096 bins (256 thr x 16, int4); re-zeroes g_cnt for the
// next run (graph replays re-execute the whole sequence).
// ---------------------------------------------------------------------------
__global__ __launch_bounds__(256) void scan_kernel() {
    __shared__ int wsum[8];
    const int t = threadIdx.x, lane = t & 31, w = t >> 5;
    int vals[16];
    #pragma unroll
    for (int k = 0; k < 4; ++k) {
        const int4 v = *(const int4*)&g_cnt[t * 16 + k * 4];
        vals[k * 4 + 0] = v.x; vals[k * 4 + 1] = v.y;
        vals[k * 4 + 2] = v.z; vals[k * 4 + 3] = v.w;
    }
    #pragma unroll
    for (int k = 0; k < 4; ++k)
        *(int4*)&g_cnt[t * 16 + k * 4] = make_int4(0, 0, 0, 0);
    int sum = 0;
    int pre[16];
    #pragma unroll
    for (int k = 0; k < 16; ++k) { pre[k] = sum; sum += vals[k]; }
    int incl = sum;
    #pragma unroll
    for (int off = 1; off < 32; off <<= 1) {
        const int x = __shfl_up_sync(0xffffffffu, incl, off);
        if (lane >= off) incl += x;
    }
    if (lane == 31) wsum[w] = incl;
    __syncthreads();
    if (t == 0) {
        int acc = 0;
        #pragma unroll
        for (int i = 0; i < 8; ++i) { const int x = wsum[i]; wsum[i] = acc; acc += x; }
        g_start[BINS] = acc;
    }
    __syncthreads();
    const int excl = wsum[w] + incl - sum;
    #pragma unroll
    for (int k = 0; k < 4; ++k) {
        int4 o;
        o.x = excl + pre[k * 4 + 0]; o.y = excl + pre[k * 4 + 1];
        o.z = excl + pre[k * 4 + 2]; o.w = excl + pre[k * 4 + 3];
        *(int4*)&g_start[t * 16 + k * 4] = o;
    }
}

// Atomic-free scatter: slot = g_start[bin] + rank (rank captured in prep).
// 2 points per thread for MLP; pid packed into spts.w.
__global__ __launch_bounds__(256) void scatter_kernel() {
    const int t0 = blockIdx.x * blockDim.x + threadIdx.x;
    #pragma unroll
    for (int k = 0; k < 2; ++k) {
        const int t = t0 + k * (NPTS / 2);
        const int br = g_binid[t];
        const int pos = g_start[br & 4095] + (br >> 12);
        float4 p = g_pts[t];
        p.w = __int_as_float(t & (Nn - 1));
        g_spts[pos] = p;
    }
}

// ---------------------------------------------------------------------------
// Fused select + output (R11 structure). Block = 256 thr = 8 warps = 8 queries.
// Select: warp-per-query ball query with per-cell ball-intersection culling
//         + warp bitonic sort-128.
// Output: scalar smem (conflict-free), 4 pair-iterations, software-pipelined
//         gather (next iteration's LDG issued before the stage barrier).
// ---------------------------------------------------------------------------
__global__ __launch_bounds__(256, 5) void group_kernel(
    const float* __restrict__ new_xyz,
    float* __restrict__ out)
{
    const int b      = blockIdx.y;
    const int m_base = blockIdx.x * 8;
    const int tid    = threadIdx.x;
    const int wid    = tid >> 5;
    const int lane   = tid & 31;

    __shared__ int    cand[8][CAP];
    __shared__ int    idx_sh[8][Kk];
    __shared__ float4 q_sh[8];
    __shared__ float  g_s[2][3][Kk];
    __shared__ float  f_s[2][Kk][Cc + 1];

    // ---- SELECT (warp <-> query) ----
    const int m = m_base + wid;
    const float qx = new_xyz[(b * 3 + 0) * Mm + m];
    const float qy = new_xyz[(b * 3 + 1) * Mm + m];
    const float qz = new_xyz[(b * 3 + 2) * Mm + m];
    const float m2 = __fadd_rn(__fadd_rn(__fmul_rn(qx, qx), __fmul_rn(qy, qy)),
                               __fmul_rn(qz, qz));
    if (lane == 0) q_sh[wid] = make_float4(qx, qy, qz, m2);

    const int qcx = min(Gg - 1, max(0, (int)(qx * Gg)));
    const int qcy = min(Gg - 1, max(0, (int)(qy * Gg)));
    const int qcz = min(Gg - 1, max(0, (int)(qz * Gg)));
    const unsigned lmask_lt = (1u << lane) - 1u;

    // Face distances to the +/-1 cell rings (cell size h = 0.125).
    constexpr float Hh  = 0.125f;
    constexpr float R2M = 0.0101f;   // cull bound: 0.01 + margin >> fp error (~2e-6)
    const float dxl = qx - qcx * Hh,  dxh = (qcx + 1) * Hh - qx;
    const float dyl = qy - qcy * Hh,  dyh = (qcy + 1) * Hh - qy;
    const float dzl = qz - qcz * Hh,  dzh = (qcz + 1) * Hh - qz;
    const float dxl2 = dxl * dxl, dxh2 = dxh * dxh;
    const float dyl2 = dyl * dyl, dyh2 = dyh * dyh;
    const float dzl2 = dzl * dzl, dzh2 = dzh * dzh;

    const int z0 = max(0, qcz - 1), z1 = min(Gg - 1, qcz + 1);
    const int y0 = max(0, qcy - 1), y1 = min(Gg - 1, qcy + 1);

    int cand_cnt = 0;
    for (int cz = z0; cz <= z1; ++cz) {
        const float dz2 = (cz < qcz) ? dzl2 : ((cz > qcz) ? dzh2 : 0.0f);
        for (int cy = y0; cy <= y1; ++cy) {
            const float dy2 = (cy < qcy) ? dyl2 : ((cy > qcy) ? dyh2 : 0.0f);
            const float dyz2 = dy2 + dz2;
            if (dyz2 >= R2M) continue;                     // row can't touch the ball
            int xlo = qcx, xhi = qcx;
            if (qcx > 0        && dxl2 + dyz2 < R2M) xlo = qcx - 1;
            if (qcx < Gg - 1   && dxh2 + dyz2 < R2M) xhi = qcx + 1;
            const int row = b * CELLS + (cz * Gg + cy) * Gg;
            const int s = g_start[row + xlo];
            const int e = g_start[row + xhi + 1];          // x-cells contiguous
            for (int base = s; base < e; base += 32) {
                const int i = base + lane;
                bool in = false;
                int pid = 0;
                if (i < e) {
                    const float4 p = g_spts[i];
                    pid = __float_as_int(p.w);
                    // n2 recomputed with the exact reference rounding chain
                    const float n2 = __fadd_rn(__fadd_rn(__fmul_rn(p.x, p.x),
                                                         __fmul_rn(p.y, p.y)),
                                               __fmul_rn(p.z, p.z));
                    const float dot = __fmaf_rn(qz, p.z,
                                      __fmaf_rn(qy, p.y, __fmul_rn(qx, p.x)));
                    const float d2  = __fsub_rn(__fadd_rn(m2, n2), __fmul_rn(2.0f, dot));
                    in = d2 < 0.01f;
                }
                const unsigned mask = __ballot_sync(0xffffffffu, in);
                if (in) {
                    const int pos = cand_cnt + __popc(mask & lmask_lt);
                    if (pos < CAP) cand[wid][pos] = pid;
                }
                cand_cnt += __popc(mask);
            }
        }
    }
    if (cand_cnt > CAP) cand_cnt = CAP;

    // ---- Warp bitonic sort of 128 values (4/lane, blocked: i = lane*4+k) ----
    int a[4];
    #pragma unroll
    for (int k = 0; k < 4; ++k) {
        const int p = lane * 4 + k;
        a[k] = (p < cand_cnt) ? cand[wid][p] : SENT;
    }
    {   // lane-local sort-4 ascending (replaces bitonic sizes 2 and 4)
        int lo, hi;
        lo = min(a[0], a[1]); hi = max(a[0], a[1]); a[0] = lo; a[1] = hi;
        lo = min(a[2], a[3]); hi = max(a[2], a[3]); a[2] = lo; a[3] = hi;
        lo = min(a[0], a[2]); hi = max(a[0], a[2]); a[0] = lo; a[2] = hi;
        lo = min(a[1], a[3]); hi = max(a[1], a[3]); a[1] = lo; a[3] = hi;
        lo = min(a[1], a[2]); hi = max(a[1], a[2]); a[1] = lo; a[2] = hi;
        if (lane & 1) {   // odd lanes descending -> alternating 4-runs
            int t0 = a[0]; a[0] = a[3]; a[3] = t0;
            int t1 = a[1]; a[1] = a[2]; a[2] = t1;
        }
    }
    #pragma unroll
    for (int size = 8; size <= 128; size <<= 1) {
        const bool dirUp = (lane & (size >> 2)) == 0;   // (i & size) == 0
        #pragma unroll
        for (int stride = size >> 1; stride >= 4; stride >>= 1) {
            const int  xl      = stride >> 2;
            const bool keepMin = (dirUp == ((lane & xl) == 0));
            #pragma unroll
            for (int k = 0; k < 4; ++k) {
                const int w = __shfl_xor_sync(0xffffffffu, a[k], xl);
                a[k] = keepMin ? min(a[k], w) : max(a[k], w);
            }
        }
        {   // stride 2: pairs (0,2),(1,3)
            int lo0 = min(a[0], a[2]), hi0 = max(a[0], a[2]);
            int lo1 = min(a[1], a[3]), hi1 = max(a[1], a[3]);
            a[0] = dirUp ? lo0 : hi0;  a[2] = dirUp ? hi0 : lo0;
            a[1] = dirUp ? lo1 : hi1;  a[3] = dirUp ? hi1 : lo1;
        }
        {   // stride 1: pairs (0,1),(2,3)
            int lo0 = min(a[0], a[1]), hi0 = max(a[0], a[1]);
            int lo1 = min(a[2], a[3]), hi1 = max(a[2], a[3]);
            a[0] = dirUp ? lo0 : hi0;  a[1] = dirUp ? hi0 : lo0;
            a[2] = dirUp ? lo1 : hi1;  a[3] = dirUp ? hi1 : lo1;
        }
    }
    // Fully ascending: smallest 32 live in lanes 0-7. Pad + publish.
    {
        int first = __shfl_sync(0xffffffffu, a[0], 0);
        first = (first >= Nn) ? 0 : first;
        if (lane < 8) {
            #pragma unroll
            for (int k = 0; k < 4; ++k) {
                const int v = (a[k] >= Nn) ? first : a[k];
                idx_sh[wid][lane * 4 + k] = v;
            }
        }
    }
    __syncthreads();

    // ---- OUTPUT: 4 pair-iterations, software-pipelined gather ----
    const float4* __restrict__ pts = g_pts + b * Nn;
    const float4* __restrict__ ft4 = (const float4*)(g_feat_t + (size_t)b * Nn * Cc);
    const size_t GX = (size_t)Bb * 67 * Mm * Kk;

    // Per-thread staging coordinates (loop-invariant): items l = tid + k*256.
    int   sq[4], sj[4], sc[4];
    #pragma unroll
    for (int k = 0; k < 4; ++k) {
        const int l = tid + k * 256;
        sq[k] = l >> 9;            // 0 for k=0,1 ; 1 for k=2,3
        sj[k] = (l >> 4) & 31;
        sc[k] = l & 15;            // float4 channel group
    }

    // Preload pq = 0
    float4 r[4];
    #pragma unroll
    for (int k = 0; k < 4; ++k)
        r[k] = ft4[(size_t)idx_sh[sq[k]][sj[k]] * 16 + sc[k]];

    #pragma unroll 1
    for (int pq = 0; pq < 4; ++pq) {
        const int q0 = pq * 2;

        if (tid < 2 * Kk) {
            const int q = tid >> 5, j = tid & 31;
            const float4 p  = pts[idx_sh[q0 + q][j]];
            const float4 Qd = q_sh[q0 + q];
            g_s[q][0][j] = __fsub_rn(p.x, Qd.x);
            g_s[q][1][j] = __fsub_rn(p.y, Qd.y);
            g_s[q][2][j] = __fsub_rn(p.z, Qd.z);
        }
        // commit preloaded registers to smem (STS only)
        #pragma unroll
        for (int k = 0; k < 4; ++k) {
            const int c4 = sc[k] * 4;
            f_s[sq[k]][sj[k]][c4 + 0] = r[k].x;
            f_s[sq[k]][sj[k]][c4 + 1] = r[k].y;
            f_s[sq[k]][sj[k]][c4 + 2] = r[k].z;
            f_s[sq[k]][sj[k]][c4 + 3] = r[k].w;
        }
        // issue next iteration's gather now: latency overlaps the write phase
        if (pq < 3) {
            #pragma unroll
            for (int k = 0; k < 4; ++k)
                r[k] = ft4[(size_t)idx_sh[q0 + 2 + sq[k]][sj[k]] * 16 + sc[k]];
        }
        __syncthreads();

        // feature channels c<64: float4 streaming writes over j
        #pragma unroll
        for (int o = tid; o < Cc * 2 * 8; o += 256) {
            const int c = o >> 4, q = (o >> 3) & 1, j4 = (o & 7) * 4;
            float4 v;
            v.x = f_s[q][j4 + 0][c]; v.y = f_s[q][j4 + 1][c];
            v.z = f_s[q][j4 + 2][c]; v.w = f_s[q][j4 + 3][c];
            __stcs((float4*)&out[(((size_t)(b * 67 + c)) * Mm + m_base + q0 + q) * Kk + j4], v);
        }
        // xyz channels (64..66) + appended group_xyz
        if (tid < 2 * 3 * Kk) {
            const int q = tid / 96, rr = tid % 96;
            const int axis = rr >> 5, j = rr & 31;
            const float v = g_s[q][axis][j];
            const size_t mq = m_base + q0 + q;
            __stcs(&out[(((size_t)(b * 67 + 64 + axis)) * Mm + mq) * Kk + j], v);
            __stcs(&out[GX + (((size_t)(b * 3 + axis)) * Mm + mq) * Kk + j], v);
        }
        __syncthreads();   // before reusing f_s / g_s
    }
}

// ---------------------------------------------------------------------------
extern "C" void kernel_launch(void* const* d_in, const int* in_sizes, int n_in,
                              void* d_out, int out_size) {
    const float* new_xyz = (const float*)d_in[0];   // (8, 3, 2048)
    const float* xyz     = (const float*)d_in[1];   // (8, 3, 8192)
    const float* feat    = (const float*)d_in[2];   // (8, 64, 8192)
    float* out = (float*)d_out;

    prep_transpose_kernel<<<TP_BLOCKS + NPTS / 256, 256>>>(xyz, feat);
    scan_kernel<<<1, 256>>>();
    scatter_kernel<<<(NPTS / 2) / 256, 256>>>();
    group_kernel<<<dim3(Mm / 8, Bb), 256>>>(new_xyz, out);
}

// round 16
// speedup vs baseline: 1.1966x; 1.0465x over previous
#include <cuda_runtime.h>
#include <cuda_bf16.h>

// Problem constants (fixed by dataset)
constexpr int Bb = 8;
constexpr int Nn = 8192;
constexpr int Mm = 2048;
constexpr int Cc = 64;
constexpr int Kk = 32;

// Spatial grid: 8x8x8 cells of 0.125 (>= radius 0.1 -> 27-cell neighborhood exact)
constexpr int Gg    = 8;
constexpr int CELLS = Gg * Gg * Gg;        // 512
constexpr int BINS  = Bb * CELLS;          // 4096
constexpr int NPTS  = Bb * Nn;             // 65536
constexpr int CAP   = 128;                 // max hits/query (lambda~34)
constexpr int CB    = 64;                  // fixed slots per cell (lambda~16, +12 sigma)
constexpr int SENT  = 0x3FFFFFFF;

// Scratch (__device__ globals: no allocs allowed; zero-initialized at load)
__device__ float  g_feat_t[Bb * Nn * Cc];            // transposed features (B,N,C)
__device__ float4 g_pts[NPTS];                       // (x,y,z,n2) original order
__device__ __align__(16) int g_cnt[BINS];            // per-cell counts (zeroed each run)
__device__ float4 g_cellpts[BINS * CB];              // fixed-slot cells (x,y,z,pid), 4MB

// ---------------------------------------------------------------------------
__global__ void zero_kernel() {
    const int t = blockIdx.x * blockDim.x + threadIdx.x;
    if (t < BINS / 4) *(int4*)&g_cnt[t * 4] = make_int4(0, 0, 0, 0);
}

// ---------------------------------------------------------------------------
// Fused: blocks [0, 1024) transpose feature (B,C,N)->(B,N,C) in 64x64 tiles;
// blocks [1024, 1280) pack points + write directly into fixed-slot cells.
// ---------------------------------------------------------------------------
constexpr int TP_BLOCKS = (Nn / 64) * Bb;   // 1024

__global__ __launch_bounds__(256) void prep_transpose_kernel(
    const float* __restrict__ xyz, const float* __restrict__ feat)
{
    __shared__ float tile[64][65];
    const int t = threadIdx.x;

    if (blockIdx.x < TP_BLOCKS) {
        const int b  = blockIdx.x >> 7;
        const int n0 = (blockIdx.x & 127) * 64;
        const int j4 = (t & 15) * 4;
        #pragma unroll
        for (int p = 0; p < 4; ++p) {
            const int row = p * 16 + (t >> 4);     // channel
            const float4 v = *(const float4*)&feat[((size_t)(b * Cc + row)) * Nn + n0 + j4];
            tile[row][j4 + 0] = v.x; tile[row][j4 + 1] = v.y;
            tile[row][j4 + 2] = v.z; tile[row][j4 + 3] = v.w;
        }
        __syncthreads();
        #pragma unroll
        for (int p = 0; p < 4; ++p) {
            const int r = p * 16 + (t >> 4);       // point within tile
            float4 v;
            v.x = tile[j4 + 0][r]; v.y = tile[j4 + 1][r];
            v.z = tile[j4 + 2][r]; v.w = tile[j4 + 3][r];
            *(float4*)&g_feat_t[((size_t)(b * Nn + n0 + r)) * Cc + j4] = v;
        }
    } else {
        const int i = (blockIdx.x - TP_BLOCKS) * 256 + t;   // 0 .. NPTS-1
        const int b = i >> 13;
        const int n = i & (Nn - 1);
        const float x = xyz[(b * 3 + 0) * Nn + n];
        const float y = xyz[(b * 3 + 1) * Nn + n];
        const float z = xyz[(b * 3 + 2) * Nn + n];
        g_pts[i] = make_float4(x, y, z, 0.0f);
        const int cx = min(Gg - 1, max(0, (int)(x * Gg)));
        const int cy = min(Gg - 1, max(0, (int)(y * Gg)));
        const int cz = min(Gg - 1, max(0, (int)(z * Gg)));
        const int bin = b * CELLS + ((cz * Gg + cy) * Gg + cx);
        const int rank = atomicAdd(&g_cnt[bin], 1);
        if (rank < CB)
            g_cellpts[bin * CB + rank] = make_float4(x, y, z, __int_as_float(n));
    }
}

// ---------------------------------------------------------------------------
// Fused select + output. Block = 256 thr = 8 warps = 8 queries.
// Select: warp-per-query, cell-culled exact ball query over fixed-slot cells
//         + warp bitonic sort-128.
// Output: 8 single-query iterations, software-pipelined gather.
// ---------------------------------------------------------------------------
__global__ __launch_bounds__(256, 6) void group_kernel(
    const float* __restrict__ new_xyz,
    float* __restrict__ out)
{
    const int b      = blockIdx.y;
    const int m_base = blockIdx.x * 8;
    const int tid    = threadIdx.x;
    const int wid    = tid >> 5;
    const int lane   = tid & 31;

    __shared__ int    cand[8][CAP];
    __shared__ int    idx_sh[8][Kk];
    __shared__ float4 q_sh[8];
    __shared__ float  g_s[3][Kk];
    __shared__ float  f_s[Kk][Cc + 1];

    // ---- SELECT (warp <-> query) ----
    const int m = m_base + wid;
    const float qx = new_xyz[(b * 3 + 0) * Mm + m];
    const float qy = new_xyz[(b * 3 + 1) * Mm + m];
    const float qz = new_xyz[(b * 3 + 2) * Mm + m];
    const float m2 = __fadd_rn(__fadd_rn(__fmul_rn(qx, qx), __fmul_rn(qy, qy)),
                               __fmul_rn(qz, qz));
    if (lane == 0) q_sh[wid] = make_float4(qx, qy, qz, m2);

    const int qcx = min(Gg - 1, max(0, (int)(qx * Gg)));
    const int qcy = min(Gg - 1, max(0, (int)(qy * Gg)));
    const int qcz = min(Gg - 1, max(0, (int)(qz * Gg)));
    const unsigned lmask_lt = (1u << lane) - 1u;

    // Face distances to the +/-1 cell rings (cell size h = 0.125).
    constexpr float Hh  = 0.125f;
    constexpr float R2M = 0.0101f;   // cull bound: 0.01 + margin >> fp error (~2e-6)
    const float dxl = qx - qcx * Hh,  dxh = (qcx + 1) * Hh - qx;
    const float dyl = qy - qcy * Hh,  dyh = (qcy + 1) * Hh - qy;
    const float dzl = qz - qcz * Hh,  dzh = (qcz + 1) * Hh - qz;
    const float dxl2 = dxl * dxl, dxh2 = dxh * dxh;
    const float dyl2 = dyl * dyl, dyh2 = dyh * dyh;
    const float dzl2 = dzl * dzl, dzh2 = dzh * dzh;

    const int z0 = max(0, qcz - 1), z1 = min(Gg - 1, qcz + 1);
    const int y0 = max(0, qcy - 1), y1 = min(Gg - 1, qcy + 1);

    int cand_cnt = 0;
    for (int cz = z0; cz <= z1; ++cz) {
        const float dz2 = (cz < qcz) ? dzl2 : ((cz > qcz) ? dzh2 : 0.0f);
        for (int cy = y0; cy <= y1; ++cy) {
            const float dy2 = (cy < qcy) ? dyl2 : ((cy > qcy) ? dyh2 : 0.0f);
            const float dyz2 = dy2 + dz2;
            if (dyz2 >= R2M) continue;                     // row can't touch the ball
            int xlo = qcx, xhi = qcx;
            if (qcx > 0        && dxl2 + dyz2 < R2M) xlo = qcx - 1;
            if (qcx < Gg - 1   && dxh2 + dyz2 < R2M) xhi = qcx + 1;
            const int row = b * CELLS + (cz * Gg + cy) * Gg;
            for (int cx = xlo; cx <= xhi; ++cx) {
                const int cell = row + cx;
                const int e = min(g_cnt[cell], CB);        // warp-uniform
                const float4* __restrict__ cp = g_cellpts + (size_t)cell * CB;
                for (int base = 0; base < e; base += 32) {
                    const int i = base + lane;
                    bool in = false;
                    int pid = 0;
                    if (i < e) {
                        const float4 p = cp[i];
                        pid = __float_as_int(p.w);
                        // n2 recomputed with the exact reference rounding chain
                        const float n2 = __fadd_rn(__fadd_rn(__fmul_rn(p.x, p.x),
                                                             __fmul_rn(p.y, p.y)),
                                                   __fmul_rn(p.z, p.z));
                        const float dot = __fmaf_rn(qz, p.z,
                                          __fmaf_rn(qy, p.y, __fmul_rn(qx, p.x)));
                        const float d2  = __fsub_rn(__fadd_rn(m2, n2),
                                                    __fmul_rn(2.0f, dot));
                        in = d2 < 0.01f;
                    }
                    const unsigned mask = __ballot_sync(0xffffffffu, in);
                    if (in) {
                        const int pos = cand_cnt + __popc(mask & lmask_lt);
                        if (pos < CAP) cand[wid][pos] = pid;
                    }
                    cand_cnt += __popc(mask);
                }
            }
        }
    }
    if (cand_cnt > CAP) cand_cnt = CAP;

    // ---- Warp bitonic sort of 128 values (4/lane, blocked: i = lane*4+k) ----
    int a[4];
    #pragma unroll
    for (int k = 0; k < 4; ++k) {
        const int p = lane * 4 + k;
        a[k] = (p < cand_cnt) ? cand[wid][p] : SENT;
    }
    {   // lane-local sort-4 ascending (replaces bitonic sizes 2 and 4)
        int lo, hi;
        lo = min(a[0], a[1]); hi = max(a[0], a[1]); a[0] = lo; a[1] = hi;
        lo = min(a[2], a[3]); hi = max(a[2], a[3]); a[2] = lo; a[3] = hi;
        lo = min(a[0], a[2]); hi = max(a[0], a[2]); a[0] = lo; a[2] = hi;
        lo = min(a[1], a[3]); hi = max(a[1], a[3]); a[1] = lo; a[3] = hi;
        lo = min(a[1], a[2]); hi = max(a[1], a[2]); a[1] = lo; a[2] = hi;
        if (lane & 1) {   // odd lanes descending -> alternating 4-runs
            int t0 = a[0]; a[0] = a[3]; a[3] = t0;
            int t1 = a[1]; a[1] = a[2]; a[2] = t1;
        }
    }
    #pragma unroll
    for (int size = 8; size <= 128; size <<= 1) {
        const bool dirUp = (lane & (size >> 2)) == 0;   // (i & size) == 0
        #pragma unroll
        for (int stride = size >> 1; stride >= 4; stride >>= 1) {
            const int  xl      = stride >> 2;
            const bool keepMin = (dirUp == ((lane & xl) == 0));
            #pragma unroll
            for (int k = 0; k < 4; ++k) {
                const int w = __shfl_xor_sync(0xffffffffu, a[k], xl);
                a[k] = keepMin ? min(a[k], w) : max(a[k], w);
            }
        }
        {   // stride 2: pairs (0,2),(1,3)
            int lo0 = min(a[0], a[2]), hi0 = max(a[0], a[2]);
            int lo1 = min(a[1], a[3]), hi1 = max(a[1], a[3]);
            a[0] = dirUp ? lo0 : hi0;  a[2] = dirUp ? hi0 : lo0;
            a[1] = dirUp ? lo1 : hi1;  a[3] = dirUp ? hi1 : lo1;
        }
        {   // stride 1: pairs (0,1),(2,3)
            int lo0 = min(a[0], a[1]), hi0 = max(a[0], a[1]);
            int lo1 = min(a[2], a[3]), hi1 = max(a[2], a[3]);
            a[0] = dirUp ? lo0 : hi0;  a[1] = dirUp ? hi0 : lo0;
            a[2] = dirUp ? lo1 : hi1;  a[3] = dirUp ? hi1 : lo1;
        }
    }
    // Fully ascending: smallest 32 live in lanes 0-7. Pad + publish.
    {
        int first = __shfl_sync(0xffffffffu, a[0], 0);
        first = (first >= Nn) ? 0 : first;
        if (lane < 8) {
            #pragma unroll
            for (int k = 0; k < 4; ++k) {
                const int v = (a[k] >= Nn) ? first : a[k];
                idx_sh[wid][lane * 4 + k] = v;
            }
        }
    }
    __syncthreads();

    // ---- OUTPUT: 8 single-query iterations, software-pipelined gather ----
    const float4* __restrict__ pts = g_pts + b * Nn;
    const float4* __restrict__ ft4 = (const float4*)(g_feat_t + (size_t)b * Nn * Cc);
    const size_t GX = (size_t)Bb * 67 * Mm * Kk;

    // Per-thread staging coordinates (loop-invariant): items l = tid + k*256.
    int sj[2], sc[2];
    #pragma unroll
    for (int k = 0; k < 2; ++k) {
        const int l = tid + k * 256;
        sj[k] = l >> 4;            // neighbor 0..31
        sc[k] = l & 15;            // float4 channel group
    }

    // Preload q = 0
    float4 r[2];
    #pragma unroll
    for (int k = 0; k < 2; ++k)
        r[k] = ft4[(size_t)idx_sh[0][sj[k]] * 16 + sc[k]];

    #pragma unroll 1
    for (int q = 0; q < 8; ++q) {
        const int mq = m_base + q;

        if (tid < Kk) {
            const float4 p  = pts[idx_sh[q][tid]];
            const float4 Qd = q_sh[q];
            g_s[0][tid] = __fsub_rn(p.x, Qd.x);
            g_s[1][tid] = __fsub_rn(p.y, Qd.y);
            g_s[2][tid] = __fsub_rn(p.z, Qd.z);
        }
        // commit preloaded registers to smem (STS only)
        #pragma unroll
        for (int k = 0; k < 2; ++k) {
            const int c4 = sc[k] * 4;
            f_s[sj[k]][c4 + 0] = r[k].x;
            f_s[sj[k]][c4 + 1] = r[k].y;
            f_s[sj[k]][c4 + 2] = r[k].z;
            f_s[sj[k]][c4 + 3] = r[k].w;
        }
        // issue next iteration's gather now: latency overlaps the write phase
        if (q < 7) {
            #pragma unroll
            for (int k = 0; k < 2; ++k)
                r[k] = ft4[(size_t)idx_sh[q + 1][sj[k]] * 16 + sc[k]];
        }
        __syncthreads();

        // feature channels c<64: 2 float4 streaming writes per thread
        #pragma unroll
        for (int k = 0; k < 2; ++k) {
            const int o = tid + k * 256;
            const int c = o >> 3, j4 = (o & 7) * 4;
            float4 v;
            v.x = f_s[j4 + 0][c]; v.y = f_s[j4 + 1][c];
            v.z = f_s[j4 + 2][c]; v.w = f_s[j4 + 3][c];
            __stcs((float4*)&out[(((size_t)(b * 67 + c)) * Mm + mq) * Kk + j4], v);
        }
        // xyz channels (64..66) + appended group_xyz
        if (tid < 3 * Kk) {
            const int axis = tid >> 5, j = tid & 31;
            const float v = g_s[axis][j];
            __stcs(&out[(((size_t)(b * 67 + 64 + axis)) * Mm + mq) * Kk + j], v);
            __stcs(&out[GX + (((size_t)(b * 3 + axis)) * Mm + mq) * Kk + j], v);
        }
        __syncthreads();   // before reusing f_s / g_s
    }
}

// ---------------------------------------------------------------------------
extern "C" void kernel_launch(void* const* d_in, const int* in_sizes, int n_in,
                              void* d_out, int out_size) {
    const float* new_xyz = (const float*)d_in[0];   // (8, 3, 2048)
    const float* xyz     = (const float*)d_in[1];   // (8, 3, 8192)
    const float* feat    = (const float*)d_in[2];   // (8, 64, 8192)
    float* out = (float*)d_out;

    zero_kernel<<<4, 256>>>();
    prep_transpose_kernel<<<TP_BLOCKS + NPTS / 256, 256>>>(xyz, feat);
    group_kernel<<<dim3(Mm / 8, Bb), 256>>>(new_xyz, out);
}

// round 17
// speedup vs baseline: 1.2037x; 1.0059x over previous
#include <cuda_runtime.h>
#include <cuda_bf16.h>

// Problem constants (fixed by dataset)
constexpr int Bb = 8;
constexpr int Nn = 8192;
constexpr int Mm = 2048;
constexpr int Cc = 64;
constexpr int Kk = 32;

// Spatial grid: 8x8x8 cells of 0.125 (>= radius 0.1 -> 27-cell neighborhood exact)
constexpr int Gg    = 8;
constexpr int CELLS = Gg * Gg * Gg;        // 512
constexpr int BINS  = Bb * CELLS;          // 4096
constexpr int NPTS  = Bb * Nn;             // 65536
constexpr int CAP   = 128;                 // max hits/query (lambda~34)
constexpr int CB    = 64;                  // fixed slots per cell (lambda~16)
constexpr int SENT  = 0x3FFFFFFF;

// Scratch (__device__ globals: no allocs allowed; zero-initialized at load)
__device__ float  g_feat_t[Bb * Nn * Cc];            // transposed features (B,N,C)
__device__ float4 g_pts[NPTS];                       // (x,y,z,_) original order
__device__ __align__(16) int g_cnt[BINS];            // per-cell counts (memset each run)
__device__ float4 g_cellpts[BINS * CB];              // fixed-slot cells (x,y,z,pid), 4MB

// ---------------------------------------------------------------------------
// Fused: blocks [0, 1024) transpose feature (B,C,N)->(B,N,C) in 64x64 tiles;
// blocks [1024, 1280) pack points + write directly into fixed-slot cells.
// ---------------------------------------------------------------------------
constexpr int TP_BLOCKS = (Nn / 64) * Bb;   // 1024

__global__ __launch_bounds__(256) void prep_transpose_kernel(
    const float* __restrict__ xyz, const float* __restrict__ feat)
{
    __shared__ float tile[64][65];
    const int t = threadIdx.x;

    if (blockIdx.x < TP_BLOCKS) {
        const int b  = blockIdx.x >> 7;
        const int n0 = (blockIdx.x & 127) * 64;
        const int j4 = (t & 15) * 4;
        #pragma unroll
        for (int p = 0; p < 4; ++p) {
            const int row = p * 16 + (t >> 4);     // channel
            const float4 v = *(const float4*)&feat[((size_t)(b * Cc + row)) * Nn + n0 + j4];
            tile[row][j4 + 0] = v.x; tile[row][j4 + 1] = v.y;
            tile[row][j4 + 2] = v.z; tile[row][j4 + 3] = v.w;
        }
        __syncthreads();
        #pragma unroll
        for (int p = 0; p < 4; ++p) {
            const int r = p * 16 + (t >> 4);       // point within tile
            float4 v;
            v.x = tile[j4 + 0][r]; v.y = tile[j4 + 1][r];
            v.z = tile[j4 + 2][r]; v.w = tile[j4 + 3][r];
            *(float4*)&g_feat_t[((size_t)(b * Nn + n0 + r)) * Cc + j4] = v;
        }
    } else {
        const int i = (blockIdx.x - TP_BLOCKS) * 256 + t;   // 0 .. NPTS-1
        const int b = i >> 13;
        const int n = i & (Nn - 1);
        const float x = xyz[(b * 3 + 0) * Nn + n];
        const float y = xyz[(b * 3 + 1) * Nn + n];
        const float z = xyz[(b * 3 + 2) * Nn + n];
        g_pts[i] = make_float4(x, y, z, 0.0f);
        const int cx = min(Gg - 1, max(0, (int)(x * Gg)));
        const int cy = min(Gg - 1, max(0, (int)(y * Gg)));
        const int cz = min(Gg - 1, max(0, (int)(z * Gg)));
        const int bin = b * CELLS + ((cz * Gg + cy) * Gg + cx);
        const int rank = atomicAdd(&g_cnt[bin], 1);
        if (rank < CB)
            g_cellpts[bin * CB + rank] = make_float4(x, y, z, __int_as_float(n));
    }
}

// ---------------------------------------------------------------------------
// Fused select + output. Block = 256 thr = 8 warps = 8 queries.
// Select: lane-parallel 27-cell cull + parallel count loads, exact ball test,
//         warp bitonic sort-128.
// Output: 8 single-query iterations, software-pipelined gather.
// ---------------------------------------------------------------------------
__global__ __launch_bounds__(256, 6) void group_kernel(
    const float* __restrict__ new_xyz,
    float* __restrict__ out)
{
    const int b      = blockIdx.y;
    const int m_base = blockIdx.x * 8;
    const int tid    = threadIdx.x;
    const int wid    = tid >> 5;
    const int lane   = tid & 31;

    __shared__ int    cand[8][CAP];
    __shared__ int    idx_sh[8][Kk];
    __shared__ int    cells_c[8][28];
    __shared__ int    cnts_c[8][28];
    __shared__ float4 q_sh[8];
    __shared__ float  g_s[3][Kk];
    __shared__ float  f_s[Kk][Cc + 1];

    // ---- SELECT (warp <-> query) ----
    const int m = m_base + wid;
    const float qx = new_xyz[(b * 3 + 0) * Mm + m];
    const float qy = new_xyz[(b * 3 + 1) * Mm + m];
    const float qz = new_xyz[(b * 3 + 2) * Mm + m];
    const float m2 = __fadd_rn(__fadd_rn(__fmul_rn(qx, qx), __fmul_rn(qy, qy)),
                               __fmul_rn(qz, qz));
    if (lane == 0) q_sh[wid] = make_float4(qx, qy, qz, m2);

    const int qcx = min(Gg - 1, max(0, (int)(qx * Gg)));
    const int qcy = min(Gg - 1, max(0, (int)(qy * Gg)));
    const int qcz = min(Gg - 1, max(0, (int)(qz * Gg)));
    const unsigned lmask_lt = (1u << lane) - 1u;

    // Face distances to the +/-1 cell rings (cell size h = 0.125).
    constexpr float Hh  = 0.125f;
    constexpr float R2M = 0.0101f;   // cull bound: 0.01 + margin >> fp error (~2e-6)
    const float dxl = qx - qcx * Hh,  dxh = (qcx + 1) * Hh - qx;
    const float dyl = qy - qcy * Hh,  dyh = (qcy + 1) * Hh - qy;
    const float dzl = qz - qcz * Hh,  dzh = (qcz + 1) * Hh - qz;
    const float dxl2 = dxl * dxl, dxh2 = dxh * dxh;
    const float dyl2 = dyl * dyl, dyh2 = dyh * dyh;
    const float dzl2 = dzl * dzl, dzh2 = dzh * dzh;

    // Lane-parallel cull of the 27 neighbor cells (lane i <-> cell i, z-major)
    int myCell = -1;
    {
        const int dz = lane / 9 - 1;
        const int dy = (lane / 3) % 3 - 1;
        const int dx = lane % 3 - 1;
        const int cz = qcz + dz, cy = qcy + dy, cx = qcx + dx;
        bool ok = (lane < 27) &&
                  cz >= 0 && cz < Gg && cy >= 0 && cy < Gg && cx >= 0 && cx < Gg;
        const float ddz2 = (dz < 0) ? dzl2 : ((dz > 0) ? dzh2 : 0.0f);
        const float ddy2 = (dy < 0) ? dyl2 : ((dy > 0) ? dyh2 : 0.0f);
        const float ddx2 = (dx < 0) ? dxl2 : ((dx > 0) ? dxh2 : 0.0f);
        ok = ok && (ddx2 + ddy2 + ddz2 < R2M);
        if (ok) myCell = b * CELLS + (cz * Gg + cy) * Gg + cx;
    }
    const unsigned vmask = __ballot_sync(0xffffffffu, myCell >= 0);
    if (myCell >= 0) {
        const int pos = __popc(vmask & lmask_lt);
        cells_c[wid][pos] = myCell;
        cnts_c[wid][pos]  = min(g_cnt[myCell], CB);   // all counts loaded in parallel
    }
    const int ncells = __popc(vmask);
    __syncwarp();

    int cand_cnt = 0;
    for (int k = 0; k < ncells; ++k) {
        const int cell = cells_c[wid][k];
        const int e    = cnts_c[wid][k];
        const float4* __restrict__ cp = g_cellpts + (size_t)cell * CB;
        for (int base = 0; base < e; base += 32) {
            const int i = base + lane;
            bool in = false;
            int pid = 0;
            if (i < e) {
                const float4 p = cp[i];
                pid = __float_as_int(p.w);
                // n2 recomputed with the exact reference rounding chain
                const float n2 = __fadd_rn(__fadd_rn(__fmul_rn(p.x, p.x),
                                                     __fmul_rn(p.y, p.y)),
                                           __fmul_rn(p.z, p.z));
                const float dot = __fmaf_rn(qz, p.z,
                                  __fmaf_rn(qy, p.y, __fmul_rn(qx, p.x)));
                const float d2  = __fsub_rn(__fadd_rn(m2, n2), __fmul_rn(2.0f, dot));
                in = d2 < 0.01f;
            }
            const unsigned mask = __ballot_sync(0xffffffffu, in);
            if (in) {
                const int pos = cand_cnt + __popc(mask & lmask_lt);
                if (pos < CAP) cand[wid][pos] = pid;
            }
            cand_cnt += __popc(mask);
        }
    }
    if (cand_cnt > CAP) cand_cnt = CAP;

    // ---- Warp bitonic sort of 128 values (4/lane, blocked: i = lane*4+k) ----
    int a[4];
    #pragma unroll
    for (int k = 0; k < 4; ++k) {
        const int p = lane * 4 + k;
        a[k] = (p < cand_cnt) ? cand[wid][p] : SENT;
    }
    {   // lane-local sort-4 ascending (replaces bitonic sizes 2 and 4)
        int lo, hi;
        lo = min(a[0], a[1]); hi = max(a[0], a[1]); a[0] = lo; a[1] = hi;
        lo = min(a[2], a[3]); hi = max(a[2], a[3]); a[2] = lo; a[3] = hi;
        lo = min(a[0], a[2]); hi = max(a[0], a[2]); a[0] = lo; a[2] = hi;
        lo = min(a[1], a[3]); hi = max(a[1], a[3]); a[1] = lo; a[3] = hi;
        lo = min(a[1], a[2]); hi = max(a[1], a[2]); a[1] = lo; a[2] = hi;
        if (lane & 1) {   // odd lanes descending -> alternating 4-runs
            int t0 = a[0]; a[0] = a[3]; a[3] = t0;
            int t1 = a[1]; a[1] = a[2]; a[2] = t1;
        }
    }
    #pragma unroll
    for (int size = 8; size <= 128; size <<= 1) {
        const bool dirUp = (lane & (size >> 2)) == 0;   // (i & size) == 0
        #pragma unroll
        for (int stride = size >> 1; stride >= 4; stride >>= 1) {
            const int  xl      = stride >> 2;
            const bool keepMin = (dirUp == ((lane & xl) == 0));
            #pragma unroll
            for (int k = 0; k < 4; ++k) {
                const int w = __shfl_xor_sync(0xffffffffu, a[k], xl);
                a[k] = keepMin ? min(a[k], w) : max(a[k], w);
            }
        }
        {   // stride 2: pairs (0,2),(1,3)
            int lo0 = min(a[0], a[2]), hi0 = max(a[0], a[2]);
            int lo1 = min(a[1], a[3]), hi1 = max(a[1], a[3]);
            a[0] = dirUp ? lo0 : hi0;  a[2] = dirUp ? hi0 : lo0;
            a[1] = dirUp ? lo1 : hi1;  a[3] = dirUp ? hi1 : lo1;
        }
        {   // stride 1: pairs (0,1),(2,3)
            int lo0 = min(a[0], a[1]), hi0 = max(a[0], a[1]);
            int lo1 = min(a[2], a[3]), hi1 = max(a[2], a[3]);
            a[0] = dirUp ? lo0 : hi0;  a[1] = dirUp ? hi0 : lo0;
            a[2] = dirUp ? lo1 : hi1;  a[3] = dirUp ? hi1 : lo1;
        }
    }
    // Fully ascending: smallest 32 live in lanes 0-7. Pad + publish.
    {
        int first = __shfl_sync(0xffffffffu, a[0], 0);
        first = (first >= Nn) ? 0 : first;
        if (lane < 8) {
            #pragma unroll
            for (int k = 0; k < 4; ++k) {
                const int v = (a[k] >= Nn) ? first : a[k];
                idx_sh[wid][lane * 4 + k] = v;
            }
        }
    }
    __syncthreads();

    // ---- OUTPUT: 8 single-query iterations, software-pipelined gather ----
    const float4* __restrict__ pts = g_pts + b * Nn;
    const float4* __restrict__ ft4 = (const float4*)(g_feat_t + (size_t)b * Nn * Cc);
    const size_t GX = (size_t)Bb * 67 * Mm * Kk;

    // Per-thread staging coordinates (loop-invariant): items l = tid + k*256.
    int sj[2], sc[2];
    #pragma unroll
    for (int k = 0; k < 2; ++k) {
        const int l = tid + k * 256;
        sj[k] = l >> 4;            // neighbor 0..31
        sc[k] = l & 15;            // float4 channel group
    }

    // Preload q = 0
    float4 r[2];
    #pragma unroll
    for (int k = 0; k < 2; ++k)
        r[k] = ft4[(size_t)idx_sh[0][sj[k]] * 16 + sc[k]];

    #pragma unroll 1
    for (int q = 0; q < 8; ++q) {
        const int mq = m_base + q;

        if (tid < Kk) {
            const float4 p  = pts[idx_sh[q][tid]];
            const float4 Qd = q_sh[q];
            g_s[0][tid] = __fsub_rn(p.x, Qd.x);
            g_s[1][tid] = __fsub_rn(p.y, Qd.y);
            g_s[2][tid] = __fsub_rn(p.z, Qd.z);
        }
        // commit preloaded registers to smem (STS only)
        #pragma unroll
        for (int k = 0; k < 2; ++k) {
            const int c4 = sc[k] * 4;
            f_s[sj[k]][c4 + 0] = r[k].x;
            f_s[sj[k]][c4 + 1] = r[k].y;
            f_s[sj[k]][c4 + 2] = r[k].z;
            f_s[sj[k]][c4 + 3] = r[k].w;
        }
        // issue next iteration's gather now: latency overlaps the write phase
        if (q < 7) {
            #pragma unroll
            for (int k = 0; k < 2; ++k)
                r[k] = ft4[(size_t)idx_sh[q + 1][sj[k]] * 16 + sc[k]];
        }
        __syncthreads();

        // feature channels c<64: 2 float4 streaming writes per thread
        #pragma unroll
        for (int k = 0; k < 2; ++k) {
            const int o = tid + k * 256;
            const int c = o >> 3, j4 = (o & 7) * 4;
            float4 v;
            v.x = f_s[j4 + 0][c]; v.y = f_s[j4 + 1][c];
            v.z = f_s[j4 + 2][c]; v.w = f_s[j4 + 3][c];
            __stcs((float4*)&out[(((size_t)(b * 67 + c)) * Mm + mq) * Kk + j4], v);
        }
        // xyz channels (64..66) + appended group_xyz
        if (tid < 3 * Kk) {
            const int axis = tid >> 5, j = tid & 31;
            const float v = g_s[axis][j];
            __stcs(&out[(((size_t)(b * 67 + 64 + axis)) * Mm + mq) * Kk + j], v);
            __stcs(&out[GX + (((size_t)(b * 3 + axis)) * Mm + mq) * Kk + j], v);
        }
        __syncthreads();   // before reusing f_s / g_s
    }
}

// ---------------------------------------------------------------------------
extern "C" void kernel_launch(void* const* d_in, const int* in_sizes, int n_in,
                              void* d_out, int out_size) {
    const float* new_xyz = (const float*)d_in[0];   // (8, 3, 2048)
    const float* xyz     = (const float*)d_in[1];   // (8, 3, 8192)
    const float* feat    = (const float*)d_in[2];   // (8, 64, 8192)
    float* out = (float*)d_out;

    // Zero the per-cell counters via a memset node (cheaper than a kernel).
    void* cnt_ptr = nullptr;
    cudaGetSymbolAddress(&cnt_ptr, g_cnt);
    cudaMemsetAsync(cnt_ptr, 0, BINS * sizeof(int));

    prep_transpose_kernel<<<TP_BLOCKS + NPTS / 256, 256>>>(xyz, feat);
    group_kernel<<<dim3(Mm / 8, Bb), 256>>>(new_xyz, out);
}